// round 3
// baseline (speedup 1.0000x reference)
#include <cuda_runtime.h>

typedef unsigned long long u64t;

// ---------------- scratch (static device allocations — allowed) ----------------
static __device__ __align__(16) float g_Wbig[512 * 128];   // [Wuc0; Wk@Wuc1; Wk@Wuc2; Wew@Wuc3]
static __device__ __align__(16) float g_b3[128];           // Web @ Wuc3
static __device__ __align__(16) float g_wqa[128];          // W_q @ a[:128]
static __device__ __align__(16) float g_wka[128];          // W_k @ a[128:]
static __device__ __align__(16) float g_hagg[2][8192][128]; // pre-W_k aggregated neighbor emb

// ---------------- packed f32x2 helpers ----------------
__device__ __forceinline__ u64t pk2(float lo, float hi) {
    u64t r; asm("mov.b64 %0, {%1,%2};" : "=l"(r) : "f"(lo), "f"(hi)); return r;
}
__device__ __forceinline__ void upk2(u64t v, float& lo, float& hi) {
    asm("mov.b64 {%0,%1}, %2;" : "=f"(lo), "=f"(hi) : "l"(v));
}
__device__ __forceinline__ u64t ffma2(u64t a, u64t b, u64t c) {
    u64t d; asm("fma.rn.f32x2 %0, %1, %2, %3;" : "=l"(d) : "l"(a), "l"(b), "l"(c)); return d;
}

// ---------------- setup: fold all the small weight algebra ----------------
__global__ void setup_kernel(const float* __restrict__ Wq, const float* __restrict__ Wk,
                             const float* __restrict__ a,  const float* __restrict__ Wew,
                             const float* __restrict__ Web, const float* __restrict__ Wuc) {
    __shared__ float rowbuf[128];
    const int i = blockIdx.x;   // output row 0..127
    const int j = threadIdx.x;  // output col 0..127

    // rows 0..127 of Wbig: copy Wuc0
    g_Wbig[i * 128 + j] = Wuc[i * 128 + j];

    // M1 = Wk @ Wuc[128:256], M2 = Wk @ Wuc[256:384]
    rowbuf[j] = Wk[i * 128 + j];
    __syncthreads();
    float acc1 = 0.f, acc2 = 0.f;
    for (int d = 0; d < 128; d++) {
        float w = rowbuf[d];
        acc1 += w * Wuc[(128 + d) * 128 + j];
        acc2 += w * Wuc[(256 + d) * 128 + j];
    }
    g_Wbig[(128 + i) * 128 + j] = acc1;
    g_Wbig[(256 + i) * 128 + j] = acc2;
    __syncthreads();

    // M3 = Wew @ Wuc[384:512]
    rowbuf[j] = Wew[i * 128 + j];
    __syncthreads();
    float acc3 = 0.f;
    for (int d = 0; d < 128; d++) acc3 += rowbuf[d] * Wuc[(384 + d) * 128 + j];
    g_Wbig[(384 + i) * 128 + j] = acc3;

    if (i == 0) {
        // b3 = Web @ Wuc3
        float b = 0.f;
        for (int d = 0; d < 128; d++) b += Web[d] * Wuc[(384 + d) * 128 + j];
        g_b3[j] = b;
        // wqa[d] = sum_e Wq[d,e]*a[e] ; wka[d] = sum_e Wk[d,e]*a[128+e]
        float q = 0.f, k2 = 0.f;
        for (int e = 0; e < 128; e++) {
            q  += Wq[j * 128 + e] * a[e];
            k2 += Wk[j * 128 + e] * a[128 + e];
        }
        g_wqa[j] = q;
        g_wka[j] = k2;
    }
}

// ---------------- attend: gather 32 neighbor rows once, softmax, weighted sum ----------------
__global__ __launch_bounds__(128) void attend_kernel(
    const float* __restrict__ memb,
    const int* __restrict__ src_idxs, const int* __restrict__ dst_idxs,
    const int* __restrict__ src_nb,   const int* __restrict__ dst_nb) {
    const int b = blockIdx.x;
    const int side = blockIdx.y;
    const int* idxs = side ? dst_idxs : src_idxs;
    const int* nbrs = side ? dst_nb   : src_nb;

    __shared__ float rows[32 * 132];  // padded stride 132 -> conflict-free column reads
    __shared__ float sk[32];
    __shared__ float attn_s[32];
    __shared__ float sqs;

    const int t = threadIdx.x;       // 128 threads
    const int j = t >> 2;            // neighbor row 0..31
    const int p = t & 3;             // quarter of the row

    // sq = self . wqa  (warp 0)
    if (t < 32) {
        const float4* self4 = (const float4*)(memb + (size_t)idxs[b] * 128);
        const float4* wq4 = (const float4*)g_wqa;
        float4 v = self4[t], w = wq4[t];
        float s = v.x * w.x + v.y * w.y + v.z * w.z + v.w * w.w;
        #pragma unroll
        for (int o = 16; o; o >>= 1) s += __shfl_xor_sync(0xffffffffu, s, o);
        if (t == 0) sqs = s;
    }

    // gather neighbor rows + dot with wka on the fly
    const int nbr = nbrs[b * 32 + j];
    const float4* r4 = (const float4*)(memb + (size_t)nbr * 128);
    const float4* wk4 = (const float4*)g_wka;
    float part = 0.f;
    #pragma unroll
    for (int i = 0; i < 8; i++) {
        float4 v = r4[p * 8 + i];
        float4 w = wk4[p * 8 + i];
        part += v.x * w.x + v.y * w.y + v.z * w.z + v.w * w.w;
        *(float4*)&rows[j * 132 + p * 32 + i * 4] = v;
    }
    part += __shfl_xor_sync(0xffffffffu, part, 1);
    part += __shfl_xor_sync(0xffffffffu, part, 2);
    if (p == 0) sk[j] = part;
    __syncthreads();

    // softmax over 32 scores (warp 0)
    if (t < 32) {
        float s = sqs + sk[t];
        s = s > 0.f ? s : 0.2f * s;          // leaky_relu(., 0.2)
        float m = s;
        #pragma unroll
        for (int o = 16; o; o >>= 1) m = fmaxf(m, __shfl_xor_sync(0xffffffffu, m, o));
        float e = expf(s - m);
        float sum = e;
        #pragma unroll
        for (int o = 16; o; o >>= 1) sum += __shfl_xor_sync(0xffffffffu, sum, o);
        attn_s[t] = e / sum;
    }
    __syncthreads();

    // h_pre[d] = sum_j attn[j] * nb_row[j][d]   (agg@W_k folded into Wbig downstream)
    float acc = 0.f;
    #pragma unroll
    for (int jj = 0; jj < 32; jj++) acc += attn_s[jj] * rows[jj * 132 + t];
    g_hagg[side][b][t] = acc;
}

// ---------------- fused MLP: msg -> Wc1 -> Wc2 for both sides ----------------
// smem layout (floats): S0,S1,H0,H1,ED,MSG,TB each 32x132
#define SMF_OFF(n) ((n) * 4224)
#define FINAL_SMEM_BYTES (7 * 4224 * 4)

__global__ __launch_bounds__(256) void final_kernel(
    const float* __restrict__ memb, const float* __restrict__ edge_feat,
    const float* __restrict__ Wc1,  const float* __restrict__ Wc2,
    const int* __restrict__ src_idxs, const int* __restrict__ dst_idxs,
    const int* __restrict__ edge_idxs, float* __restrict__ out) {
    extern __shared__ float sm[];
    float* S0  = sm + SMF_OFF(0);
    float* S1  = sm + SMF_OFF(1);
    float* H0  = sm + SMF_OFF(2);
    float* H1  = sm + SMF_OFF(3);
    float* ED  = sm + SMF_OFF(4);
    float* MSG = sm + SMF_OFF(5);
    float* TB  = sm + SMF_OFF(6);

    const int t = threadIdx.x;
    const int b0 = blockIdx.x * 32;

    // ---- load phase: 5 arrays of 32x128 ----
    {
        const int r = t >> 3, q = t & 7;
        const float4* s; float4* d;
        s = (const float4*)(memb + (size_t)src_idxs[b0 + r] * 128);
        d = (float4*)(S0 + r * 132);
        #pragma unroll
        for (int i = 0; i < 4; i++) d[q * 4 + i] = s[q * 4 + i];

        s = (const float4*)(memb + (size_t)dst_idxs[b0 + r] * 128);
        d = (float4*)(S1 + r * 132);
        #pragma unroll
        for (int i = 0; i < 4; i++) d[q * 4 + i] = s[q * 4 + i];

        s = (const float4*)(edge_feat + (size_t)edge_idxs[b0 + r] * 128);
        d = (float4*)(ED + r * 132);
        #pragma unroll
        for (int i = 0; i < 4; i++) d[q * 4 + i] = s[q * 4 + i];

        s = (const float4*)(&g_hagg[0][b0 + r][0]);
        d = (float4*)(H0 + r * 132);
        #pragma unroll
        for (int i = 0; i < 4; i++) d[q * 4 + i] = s[q * 4 + i];

        s = (const float4*)(&g_hagg[1][b0 + r][0]);
        d = (float4*)(H1 + r * 132);
        #pragma unroll
        for (int i = 0; i < 4; i++) d[q * 4 + i] = s[q * 4 + i];
    }
    __syncthreads();

    const int rg = t >> 4;          // 0..15 (2 rows each)
    const int cg = t & 15;          // 0..15 (8 cols each)
    const int r0 = rg * 2, r1 = r0 + 1;
    const int c0 = cg * 8;

    for (int side = 0; side < 2; side++) {
        // ---- phase 2: msg = relu(concat @ Wbig + b3) ----
        const float* seg0 = side ? S1 : S0;
        const float* seg1 = side ? H1 : H0;
        const float* seg2 = side ? H0 : H1;
        const float* segs[4] = {seg0, seg1, seg2, ED};

        u64t acc[8];
        #pragma unroll
        for (int p2 = 0; p2 < 4; p2++) {
            u64t v = *(const u64t*)(g_b3 + c0 + 2 * p2);
            acc[p2] = v; acc[4 + p2] = v;
        }
        #pragma unroll
        for (int seg = 0; seg < 4; seg++) {
            const float* A0 = segs[seg] + r0 * 132;
            const float* A1 = segs[seg] + r1 * 132;
            const ulonglong2* Wp = (const ulonglong2*)(g_Wbig + seg * 16384 + c0);
            #pragma unroll 4
            for (int kk = 0; kk < 128; kk++) {
                float xa = A0[kk], xb = A1[kk];
                u64t va = pk2(xa, xa), vb = pk2(xb, xb);
                ulonglong2 w0 = Wp[kk * 32];
                ulonglong2 w1 = Wp[kk * 32 + 1];
                acc[0] = ffma2(va, w0.x, acc[0]); acc[1] = ffma2(va, w0.y, acc[1]);
                acc[2] = ffma2(va, w1.x, acc[2]); acc[3] = ffma2(va, w1.y, acc[3]);
                acc[4] = ffma2(vb, w0.x, acc[4]); acc[5] = ffma2(vb, w0.y, acc[5]);
                acc[6] = ffma2(vb, w1.x, acc[6]); acc[7] = ffma2(vb, w1.y, acc[7]);
            }
        }
        #pragma unroll
        for (int p2 = 0; p2 < 4; p2++) {
            float lo, hi;
            upk2(acc[p2], lo, hi);
            MSG[r0 * 132 + c0 + 2 * p2]     = fmaxf(lo, 0.f);
            MSG[r0 * 132 + c0 + 2 * p2 + 1] = fmaxf(hi, 0.f);
            upk2(acc[4 + p2], lo, hi);
            MSG[r1 * 132 + c0 + 2 * p2]     = fmaxf(lo, 0.f);
            MSG[r1 * 132 + c0 + 2 * p2 + 1] = fmaxf(hi, 0.f);
        }
        __syncthreads();

        // ---- phase 3: t = relu(msg @ Wc1) ----
        {
            u64t acc2[8];
            #pragma unroll
            for (int p2 = 0; p2 < 8; p2++) acc2[p2] = 0ull;
            const float* A0 = MSG + r0 * 132;
            const float* A1 = MSG + r1 * 132;
            const ulonglong2* Wp = (const ulonglong2*)(Wc1 + c0);
            #pragma unroll 4
            for (int kk = 0; kk < 128; kk++) {
                float xa = A0[kk], xb = A1[kk];
                u64t va = pk2(xa, xa), vb = pk2(xb, xb);
                ulonglong2 w0 = Wp[kk * 32];
                ulonglong2 w1 = Wp[kk * 32 + 1];
                acc2[0] = ffma2(va, w0.x, acc2[0]); acc2[1] = ffma2(va, w0.y, acc2[1]);
                acc2[2] = ffma2(va, w1.x, acc2[2]); acc2[3] = ffma2(va, w1.y, acc2[3]);
                acc2[4] = ffma2(vb, w0.x, acc2[4]); acc2[5] = ffma2(vb, w0.y, acc2[5]);
                acc2[6] = ffma2(vb, w1.x, acc2[6]); acc2[7] = ffma2(vb, w1.y, acc2[7]);
            }
            #pragma unroll
            for (int p2 = 0; p2 < 4; p2++) {
                float lo, hi;
                upk2(acc2[p2], lo, hi);
                TB[r0 * 132 + c0 + 2 * p2]     = fmaxf(lo, 0.f);
                TB[r0 * 132 + c0 + 2 * p2 + 1] = fmaxf(hi, 0.f);
                upk2(acc2[4 + p2], lo, hi);
                TB[r1 * 132 + c0 + 2 * p2]     = fmaxf(lo, 0.f);
                TB[r1 * 132 + c0 + 2 * p2 + 1] = fmaxf(hi, 0.f);
            }
        }
        __syncthreads();

        // ---- phase 4: logits = t @ Wc2  (N=60) ----
        {
            const int c4 = cg * 4;
            float a0[4] = {0.f, 0.f, 0.f, 0.f};
            float a1[4] = {0.f, 0.f, 0.f, 0.f};
            const float* A0 = TB + r0 * 132;
            const float* A1 = TB + r1 * 132;
            #pragma unroll 4
            for (int kk = 0; kk < 128; kk++) {
                float xa = A0[kk], xb = A1[kk];
                const float* wr = Wc2 + kk * 60;
                #pragma unroll
                for (int m = 0; m < 4; m++) {
                    float w = (c4 + m < 60) ? wr[c4 + m] : 0.f;
                    a0[m] += xa * w;
                    a1[m] += xb * w;
                }
            }
            float* o0 = out + ((size_t)side * 8192 + b0 + r0) * 60;
            float* o1 = out + ((size_t)side * 8192 + b0 + r1) * 60;
            #pragma unroll
            for (int m = 0; m < 4; m++) {
                if (c4 + m < 60) { o0[c4 + m] = a0[m]; o1[c4 + m] = a1[m]; }
            }
        }
        // next side's phase 2 (MSG writes) is guarded by the sync after its own
        // compute; TB overwrite in next side's phase 3 is fenced by that side's
        // post-phase-2 __syncthreads (every thread has left phase 4 by then).
    }
}

// ---------------- launch ----------------
extern "C" void kernel_launch(void* const* d_in, const int* in_sizes, int n_in,
                              void* d_out, int out_size) {
    (void)in_sizes; (void)n_in; (void)out_size;
    const float* memb      = (const float*)d_in[0];
    const float* edge_feat = (const float*)d_in[1];
    const float* Wq        = (const float*)d_in[2];
    const float* Wk        = (const float*)d_in[3];
    const float* a         = (const float*)d_in[4];
    const float* Wew       = (const float*)d_in[5];
    const float* Web       = (const float*)d_in[6];
    const float* Wuc       = (const float*)d_in[7];
    const float* Wc1       = (const float*)d_in[8];
    const float* Wc2       = (const float*)d_in[9];
    const int* src_idxs    = (const int*)d_in[10];
    const int* dst_idxs    = (const int*)d_in[11];
    const int* edge_idxs   = (const int*)d_in[12];
    const int* src_nb      = (const int*)d_in[13];
    const int* dst_nb      = (const int*)d_in[14];
    float* out = (float*)d_out;

    setup_kernel<<<128, 128>>>(Wq, Wk, a, Wew, Web, Wuc);
    attend_kernel<<<dim3(8192, 2), 128>>>(memb, src_idxs, dst_idxs, src_nb, dst_nb);
    cudaFuncSetAttribute(final_kernel, cudaFuncAttributeMaxDynamicSharedMemorySize,
                         FINAL_SMEM_BYTES);
    final_kernel<<<256, 256, FINAL_SMEM_BYTES>>>(memb, edge_feat, Wc1, Wc2,
                                                 src_idxs, dst_idxs, edge_idxs, out);
}

// round 5
// speedup vs baseline: 2.0784x; 2.0784x over previous
#include <cuda_runtime.h>

typedef unsigned long long u64t;

// ---------------- scratch (static device globals — allowed) ----------------
static __device__ __align__(16) float g_Wbig[512 * 128];    // [Wuc0; Wk@Wuc1; Wk@Wuc2; Wew@Wuc3]
static __device__ __align__(16) float g_b3[128];            // Web @ Wuc3
static __device__ __align__(16) float g_wqa[128];           // W_q @ a[:128]
static __device__ __align__(16) float g_wka[128];           // W_k @ a[128:]
static __device__ __align__(16) float g_hagg[2][8192][128]; // pre-W_k aggregated neighbor emb

// ---------------- packed f32x2 helpers ----------------
__device__ __forceinline__ u64t pk2(float lo, float hi) {
    u64t r; asm("mov.b64 %0, {%1,%2};" : "=l"(r) : "f"(lo), "f"(hi)); return r;
}
__device__ __forceinline__ void upk2(u64t v, float& lo, float& hi) {
    asm("mov.b64 {%0,%1}, %2;" : "=f"(lo), "=f"(hi) : "l"(v));
}
__device__ __forceinline__ u64t ffma2(u64t a, u64t b, u64t c) {
    u64t d; asm("fma.rn.f32x2 %0, %1, %2, %3;" : "=l"(d) : "l"(a), "l"(b), "l"(c)); return d;
}

// ---------------- cp.async helpers ----------------
__device__ __forceinline__ unsigned smem_u32(const void* p) {
    return (unsigned)__cvta_generic_to_shared(p);
}
__device__ __forceinline__ void cpa16(unsigned d, const void* s) {
    asm volatile("cp.async.cg.shared.global [%0], [%1], 16;" :: "r"(d), "l"(s));
}
#define CP_COMMIT() asm volatile("cp.async.commit_group;" ::: "memory")
#define CP_WAIT(n)  asm volatile("cp.async.wait_group %0;" :: "n"(n) : "memory")

// ---------------- setup: fold the small weight algebra (one row per block) ----------------
__global__ __launch_bounds__(128) void setup_kernel(
    const float* __restrict__ Wq, const float* __restrict__ Wk,
    const float* __restrict__ a,  const float* __restrict__ Wew,
    const float* __restrict__ Web, const float* __restrict__ Wuc) {
    const int blk = blockIdx.x;
    const int j = threadIdx.x;

    if (blk < 128) {                       // rows 0..127: copy Wuc0
        g_Wbig[blk * 128 + j] = Wuc[blk * 128 + j];
        return;
    }
    if (blk < 512) {                       // M1 / M2 / M3 rows
        __shared__ float rowv[128];
        const int seg = blk >> 7;          // 1, 2, 3
        const int i = blk & 127;
        const float* srcrow = (seg == 3) ? (Wew + i * 128) : (Wk + i * 128);
        rowv[j] = srcrow[j];
        __syncthreads();
        const int off = seg * 128;
        float acc = 0.f;
        #pragma unroll 8
        for (int d = 0; d < 128; d++) acc += rowv[d] * Wuc[(off + d) * 128 + j];
        g_Wbig[blk * 128 + j] = acc;
        return;
    }
    // blk == 512: b3, wqa, wka
    float b = 0.f, q = 0.f, k2 = 0.f;
    #pragma unroll 8
    for (int d = 0; d < 128; d++) {
        b  += Web[d] * Wuc[(384 + d) * 128 + j];
        q  += Wq[j * 128 + d] * a[d];
        k2 += Wk[j * 128 + d] * a[128 + d];
    }
    g_b3[j] = b; g_wqa[j] = q; g_wka[j] = k2;
}

// ---------------- attend: gather 32 neighbor rows once, softmax, weighted sum ----------------
__global__ __launch_bounds__(128) void attend_kernel(
    const float* __restrict__ memb,
    const int* __restrict__ src_idxs, const int* __restrict__ dst_idxs,
    const int* __restrict__ src_nb,   const int* __restrict__ dst_nb) {
    const int b = blockIdx.x;
    const int side = blockIdx.y;
    const int* idxs = side ? dst_idxs : src_idxs;
    const int* nbrs = side ? dst_nb   : src_nb;

    __shared__ float rows[32 * 132];
    __shared__ float sk[32];
    __shared__ float attn_s[32];
    __shared__ float sqs;

    const int t = threadIdx.x;
    const int j = t >> 2;
    const int p = t & 3;

    if (t < 32) {
        const float4* self4 = (const float4*)(memb + (size_t)idxs[b] * 128);
        const float4* wq4 = (const float4*)g_wqa;
        float4 v = self4[t], w = wq4[t];
        float s = v.x * w.x + v.y * w.y + v.z * w.z + v.w * w.w;
        #pragma unroll
        for (int o = 16; o; o >>= 1) s += __shfl_xor_sync(0xffffffffu, s, o);
        if (t == 0) sqs = s;
    }

    const int nbr = nbrs[b * 32 + j];
    const float4* r4 = (const float4*)(memb + (size_t)nbr * 128);
    const float4* wk4 = (const float4*)g_wka;
    float part = 0.f;
    #pragma unroll
    for (int i = 0; i < 8; i++) {
        float4 v = r4[p * 8 + i];
        float4 w = wk4[p * 8 + i];
        part += v.x * w.x + v.y * w.y + v.z * w.z + v.w * w.w;
        *(float4*)&rows[j * 132 + p * 32 + i * 4] = v;
    }
    part += __shfl_xor_sync(0xffffffffu, part, 1);
    part += __shfl_xor_sync(0xffffffffu, part, 2);
    if (p == 0) sk[j] = part;
    __syncthreads();

    if (t < 32) {
        float s = sqs + sk[t];
        s = s > 0.f ? s : 0.2f * s;
        float m = s;
        #pragma unroll
        for (int o = 16; o; o >>= 1) m = fmaxf(m, __shfl_xor_sync(0xffffffffu, m, o));
        float e = __expf(s - m);
        float sum = e;
        #pragma unroll
        for (int o = 16; o; o >>= 1) sum += __shfl_xor_sync(0xffffffffu, sum, o);
        attn_s[t] = e / sum;
    }
    __syncthreads();

    float acc = 0.f;
    #pragma unroll
    for (int jj = 0; jj < 32; jj++) acc += attn_s[jj] * rows[jj * 132 + t];
    g_hagg[side][b][t] = acc;
}

// ---------------- fused MLP v2: 64 rows/block/side, smem-staged weights ----------------
#define FR 64
#define XSTR 516
#define XS_FLOATS (FR * XSTR)          // 33024
#define WCHUNK_FLOATS (64 * 128)       // 8192
#define FINAL_SMEM_BYTES ((XS_FLOATS + 2 * WCHUNK_FLOATS) * 4)   // 197632

// 64-k-chunk MAC: thread computes 4 rows x 8 cols
__device__ __forceinline__ void mac_chunk64(const float* __restrict__ A, int astride,
                                            const float* __restrict__ Wb, int c0,
                                            u64t acc[16]) {
    #pragma unroll 4
    for (int kk = 0; kk < 64; kk++) {
        ulonglong2 w01 = *(const ulonglong2*)(Wb + kk * 128 + c0);
        ulonglong2 w23 = *(const ulonglong2*)(Wb + kk * 128 + c0 + 4);
        #pragma unroll
        for (int i = 0; i < 4; i++) {
            float x = A[i * astride + kk];
            u64t v = pk2(x, x);
            acc[i * 4 + 0] = ffma2(v, w01.x, acc[i * 4 + 0]);
            acc[i * 4 + 1] = ffma2(v, w01.y, acc[i * 4 + 1]);
            acc[i * 4 + 2] = ffma2(v, w23.x, acc[i * 4 + 2]);
            acc[i * 4 + 3] = ffma2(v, w23.y, acc[i * 4 + 3]);
        }
    }
}

__device__ __forceinline__ void prefetchW64(const float* __restrict__ Wg, float* dstbuf, int t) {
    unsigned dbase = smem_u32(dstbuf);
    #pragma unroll
    for (int i = 0; i < 8; i++) {
        int f4 = i * 256 + t;              // 0..2047 float4s
        cpa16(dbase + f4 * 16, (const char*)Wg + f4 * 16);
    }
}

__global__ __launch_bounds__(256) void final_kernel(
    const float* __restrict__ memb, const float* __restrict__ edge_feat,
    const float* __restrict__ Wc1,  const float* __restrict__ Wc2,
    const int* __restrict__ src_idxs, const int* __restrict__ dst_idxs,
    const int* __restrict__ edge_idxs, float* __restrict__ out) {
    extern __shared__ float sm[];
    float* Xs   = sm;                      // 64 x 516 (X; later MSG @0, TB @8448)
    float* Wbuf = sm + XS_FLOATS;          // 2 x (64 x 128)

    const int t = threadIdx.x;
    const int side = blockIdx.y;
    const int b0 = blockIdx.x * FR;
    const int* idxs = side ? dst_idxs : src_idxs;

    // ---- gather X = [self | h_self | h_other | edge] : 64 x 512 ----
    {
        const int r = t >> 2, q = t & 3;
        const int b = b0 + r;
        const float4* s0 = (const float4*)(memb + (size_t)idxs[b] * 128);
        const float4* s1 = (const float4*)(&g_hagg[side][b][0]);
        const float4* s2 = (const float4*)(&g_hagg[side ^ 1][b][0]);
        const float4* s3 = (const float4*)(edge_feat + (size_t)edge_idxs[b] * 128);
        float4* d = (float4*)(Xs + r * XSTR);
        #pragma unroll
        for (int i = 0; i < 8; i++) d[q * 8 + i]      = s0[q * 8 + i];
        #pragma unroll
        for (int i = 0; i < 8; i++) d[32 + q * 8 + i] = s1[q * 8 + i];
        #pragma unroll
        for (int i = 0; i < 8; i++) d[64 + q * 8 + i] = s2[q * 8 + i];
        #pragma unroll
        for (int i = 0; i < 8; i++) d[96 + q * 8 + i] = s3[q * 8 + i];
    }

    const int rg = t >> 4;                 // 0..15, 4 rows each
    const int cg = t & 15;
    const int c0 = cg * 8;

    // ---- phase 2: MSG = relu(X @ Wbig + b3), k = 512 in 8 chunks ----
    u64t acc[16];
    #pragma unroll
    for (int p = 0; p < 4; p++) {
        u64t bv = *(const u64t*)(g_b3 + c0 + 2 * p);
        acc[p] = bv; acc[4 + p] = bv; acc[8 + p] = bv; acc[12 + p] = bv;
    }

    prefetchW64(g_Wbig, Wbuf, t); CP_COMMIT();
    __syncthreads();   // X gather visible to all before use

    #pragma unroll 1
    for (int kc = 0; kc < 8; kc++) {
        if (kc + 1 < 8) {
            prefetchW64(g_Wbig + (kc + 1) * WCHUNK_FLOATS,
                        Wbuf + ((kc + 1) & 1) * WCHUNK_FLOATS, t);
            CP_COMMIT();
            CP_WAIT(1);
        } else {
            CP_WAIT(0);
        }
        __syncthreads();
        mac_chunk64(Xs + (rg * 4) * XSTR + kc * 64, XSTR,
                    Wbuf + (kc & 1) * WCHUNK_FLOATS, c0, acc);
        __syncthreads();
    }

    // X dead now; write MSG (stride 132) into Xs[0..8448)
    float* MSG = Xs;
    #pragma unroll
    for (int i = 0; i < 4; i++) {
        float* mrow = MSG + (rg * 4 + i) * 132 + c0;
        #pragma unroll
        for (int p = 0; p < 4; p++) {
            float lo, hi; upk2(acc[i * 4 + p], lo, hi);
            mrow[2 * p]     = fmaxf(lo, 0.f);
            mrow[2 * p + 1] = fmaxf(hi, 0.f);
        }
    }
    __syncthreads();

    // ---- phase 3: TB = relu(MSG @ Wc1), k = 128 in 2 chunks ----
    u64t acc2[16];
    #pragma unroll
    for (int p = 0; p < 16; p++) acc2[p] = 0ull;

    prefetchW64(Wc1, Wbuf, t); CP_COMMIT();
    #pragma unroll 1
    for (int kc = 0; kc < 2; kc++) {
        if (kc + 1 < 2) {
            prefetchW64(Wc1 + WCHUNK_FLOATS, Wbuf + WCHUNK_FLOATS, t);
            CP_COMMIT();
            CP_WAIT(1);
        } else {
            CP_WAIT(0);
        }
        __syncthreads();
        mac_chunk64(MSG + (rg * 4) * 132 + kc * 64, 132,
                    Wbuf + (kc & 1) * WCHUNK_FLOATS, c0, acc2);
        __syncthreads();
    }

    float* TB = Xs + FR * 132;             // floats 8448..16896
    #pragma unroll
    for (int i = 0; i < 4; i++) {
        float* trow = TB + (rg * 4 + i) * 132 + c0;
        #pragma unroll
        for (int p = 0; p < 4; p++) {
            float lo, hi; upk2(acc2[i * 4 + p], lo, hi);
            trow[2 * p]     = fmaxf(lo, 0.f);
            trow[2 * p + 1] = fmaxf(hi, 0.f);
        }
    }
    __syncthreads();

    // ---- phase 4: logits = TB @ Wc2 (128 x 60), Wc2 staged whole in Wbuf ----
    for (int idx = t; idx < 128 * 60; idx += 256) Wbuf[idx] = Wc2[idx];
    __syncthreads();

    const int c4 = cg * 4;                 // cg 15 -> cols 60..63: inactive
    if (c4 < 60) {
        u64t a4[8];
        #pragma unroll
        for (int p = 0; p < 8; p++) a4[p] = 0ull;
        const float* A = TB + (rg * 4) * 132;
        #pragma unroll 4
        for (int kk = 0; kk < 128; kk++) {
            u64t w0 = *(const u64t*)(Wbuf + kk * 60 + c4);
            u64t w1 = *(const u64t*)(Wbuf + kk * 60 + c4 + 2);
            #pragma unroll
            for (int i = 0; i < 4; i++) {
                float x = A[i * 132 + kk];
                u64t v = pk2(x, x);
                a4[i * 2]     = ffma2(v, w0, a4[i * 2]);
                a4[i * 2 + 1] = ffma2(v, w1, a4[i * 2 + 1]);
            }
        }
        #pragma unroll
        for (int i = 0; i < 4; i++) {
            float l0, h0, l1, h1;
            upk2(a4[i * 2], l0, h0);
            upk2(a4[i * 2 + 1], l1, h1);
            float* o = out + ((size_t)side * 8192 + b0 + rg * 4 + i) * 60 + c4;
            *(float4*)o = make_float4(l0, h0, l1, h1);
        }
    }
}

// ---------------- launch ----------------
extern "C" void kernel_launch(void* const* d_in, const int* in_sizes, int n_in,
                              void* d_out, int out_size) {
    (void)in_sizes; (void)n_in; (void)out_size;
    const float* memb      = (const float*)d_in[0];
    const float* edge_feat = (const float*)d_in[1];
    const float* Wq        = (const float*)d_in[2];
    const float* Wk        = (const float*)d_in[3];
    const float* a         = (const float*)d_in[4];
    const float* Wew       = (const float*)d_in[5];
    const float* Web       = (const float*)d_in[6];
    const float* Wuc       = (const float*)d_in[7];
    const float* Wc1       = (const float*)d_in[8];
    const float* Wc2       = (const float*)d_in[9];
    const int* src_idxs    = (const int*)d_in[10];
    const int* dst_idxs    = (const int*)d_in[11];
    const int* edge_idxs   = (const int*)d_in[12];
    const int* src_nb      = (const int*)d_in[13];
    const int* dst_nb      = (const int*)d_in[14];
    float* out = (float*)d_out;

    setup_kernel<<<513, 128>>>(Wq, Wk, a, Wew, Web, Wuc);
    attend_kernel<<<dim3(8192, 2), 128>>>(memb, src_idxs, dst_idxs, src_nb, dst_nb);
    cudaFuncSetAttribute(final_kernel, cudaFuncAttributeMaxDynamicSharedMemorySize,
                         FINAL_SMEM_BYTES);
    final_kernel<<<dim3(128, 2), 256, FINAL_SMEM_BYTES>>>(memb, edge_feat, Wc1, Wc2,
                                                          src_idxs, dst_idxs, edge_idxs, out);
}